// round 12
// baseline (speedup 1.0000x reference)
#include <cuda_runtime.h>
#include <cstdint>

#define BGRAPHS   16
#define NPG       2048
#define N_ALL     (BGRAPHS * NPG)
#define KNN       16
#define MIN_DISTR 5
#define CPB       32                 // centers (sorted ranks) per block
#define PARTS     8                  // parts per center
#define THREADS   (CPB * PARTS)      // 256
#define WIN       512                // bound-pass window (x-nearest ranks)
#define WPP       (WIN / PARTS)      // 64 candidates per part
#define CAP       64                 // pass-2 collection capacity per center
#define MARGIN    0.05f              // covers d2-formula rounding error (<=3e-3)

// static device scratch (allocation-free): per-graph x-sorted nodes
__device__ float4         g_s4[N_ALL];   // sorted {x,y,z,|p|^2}
__device__ unsigned short g_si[N_ALL];   // sorted -> original local index

// monotone float -> uint key (total order matching float <)
__device__ __forceinline__ unsigned sortkey(float f)
{
    unsigned u = __float_as_uint(f);
    return u ^ (unsigned)(((int)u >> 31) | 0x80000000);
}

// exact reference-rounded squared distance (validated rounds 3-11)
__device__ __forceinline__ float d2_ref(float cx, float cy, float cz, float csq,
                                        const float4 v)
{
    float dot = __fmaf_rn(cz, v.z, __fmaf_rn(cy, v.y, __fmul_rn(cx, v.x)));
    return __fmaf_rn(-2.0f, dot, __fadd_rn(csq, v.w));
}

// ---------- Kernel A: per-graph bitonic sort by x ----------
__global__ __launch_bounds__(512)
void sort_kernel(const float* __restrict__ pos)
{
    __shared__ unsigned long long sk[NPG];   // 16 KB
    const int g = blockIdx.x, tid = threadIdx.x, gb = g * NPG;

    for (int i = tid; i < NPG; i += 512) {
        float x = pos[3ull * (unsigned long long)(gb + i)];
        sk[i] = ((unsigned long long)sortkey(x) << 32) | (unsigned)i;
    }
    __syncthreads();

    for (int k = 2; k <= NPG; k <<= 1) {
        for (int j = k >> 1; j > 0; j >>= 1) {
            for (int t = tid; t < NPG; t += 512) {
                int ixj = t ^ j;
                if (ixj > t) {
                    unsigned long long a = sk[t], b = sk[ixj];
                    bool up = ((t & k) == 0);
                    if ((a > b) == up) { sk[t] = b; sk[ixj] = a; }
                }
            }
            __syncthreads();
        }
    }

    for (int r = tid; r < NPG; r += 512) {
        int i = (int)(sk[r] & 0xFFFFu);
        const float* q = pos + 3ull * (unsigned long long)(gb + i);
        float x = q[0], y = q[1], z = q[2];
        float sq = __fadd_rn(__fadd_rn(__fmul_rn(x, x), __fmul_rn(y, y)),
                             __fmul_rn(z, z));
        g_s4[gb + r] = make_float4(x, y, z, sq);
        g_si[gb + r] = (unsigned short)i;
    }
}

// ---------- Kernel B: bound + windowed sweep + exact selection ----------
__global__ __launch_bounds__(THREADS, 5)
void knn_kernel(float2* __restrict__ out)
{
    __shared__ float4         s4[NPG];            // 32 KB sorted nodes
    __shared__ unsigned short si[NPG];            //  4 KB orig indices
    __shared__ float          pvals[CPB * PARTS * 3];
    __shared__ float          bnd[CPB];
    __shared__ int            cnt[CPB];
    __shared__ unsigned short jbuf[CPB * CAP];    //  4 KB

    const int tid = threadIdx.x;
    const int p   = tid >> 5;        // part (warp)
    const int c   = tid & 31;        // center-in-block (lane)

    const int g  = blockIdx.x >> 6;           // 64 blocks per graph
    const int cb = (blockIdx.x & 63) * CPB;   // sorted-rank base
    const int gb = g * NPG;

    if (tid < CPB) cnt[tid] = 0;
    for (int i = tid; i < NPG; i += THREADS) {
        s4[i] = g_s4[gb + i];
        si[i] = g_si[gb + i];
    }
    __syncthreads();

    const int    rk = cb + c;                 // this center's sorted rank
    const float4 cc = s4[rk];
    const float  cx = cc.x, cy = cc.y, cz = cc.z, csq = cc.w;
    const float  INF = __int_as_float(0x7f800000);

    // ---- pass 1 (bound): R5's 3-smallest per part over a 512 x-window ----
    // Window is block-uniform -> broadcast LDS. Any >=16-element non-self
    // subset yields a VALID upper bound on the true 16th-smallest d2.
    int w0 = cb + (CPB / 2) - WIN / 2;
    if (w0 < 0) w0 = 0;
    if (w0 > NPG - WIN) w0 = NPG - WIN;

    float h0 = INF, h1 = INF, h2 = INF;
    const int jb = w0 + p * WPP;
#pragma unroll 8
    for (int j = jb; j < jb + WPP; ++j) {
        float d2 = d2_ref(cx, cy, cz, csq, s4[j]);
        d2 = (j == rk) ? INF : d2;            // exclude self
        float t0 = fminf(h0, d2), x1 = fmaxf(h0, d2); h0 = t0;
        float t1 = fminf(h1, x1), x2 = fmaxf(h1, x1); h1 = t1;
        h2 = fminf(h2, x2);
    }
    {
        float* pv = pvals + (c * PARTS + p) * 3;
        pv[0] = h0; pv[1] = h1; pv[2] = h2;
    }
    __syncthreads();

    // 16th smallest of the 24 part-values (= 9th largest): valid bound
    if (tid < CPB) {
        float g9[9];
#pragma unroll
        for (int t = 0; t < 9; ++t) g9[t] = -INF;
        const float* pv = pvals + tid * PARTS * 3;
        for (int e = 0; e < PARTS * 3; ++e) {
            float x = pv[e];
#pragma unroll
            for (int t = 0; t < 9; ++t) {
                float hi = fmaxf(g9[t], x);
                x = fminf(g9[t], x);
                g9[t] = hi;
            }
        }
        bnd[tid] = g9[8];
    }
    __syncthreads();

    // ---- pass 2: outward sweep, stride-8 across parts, stop by (dx)^2 ----
    // x sorted => dx monotone per direction (also within each stride-8 lane).
    // Unscanned j have ideal_d2 >= dx^2 > B+MARGIN => computed_d2 > B: safe.
    const float B  = bnd[c];
    const float BM = B + MARGIN;
    for (int s = rk + 1 + p; s < NPG; s += PARTS) {
        const float4 v = s4[s];
        float dx = __fadd_rn(v.x, -cx);
        if (!(__fmul_rn(dx, dx) <= BM)) break;
        float d2 = d2_ref(cx, cy, cz, csq, v);
        if (d2 <= B) {
            int sl = atomicAdd(&cnt[c], 1);
            if (sl < CAP) jbuf[c * CAP + sl] = (unsigned short)s;
        }
    }
    for (int s = rk - 1 - p; s >= 0; s -= PARTS) {
        const float4 v = s4[s];
        float dx = __fadd_rn(cx, -v.x);
        if (!(__fmul_rn(dx, dx) <= BM)) break;
        float d2 = d2_ref(cx, cy, cz, csq, v);
        if (d2 <= B) {
            int sl = atomicAdd(&cnt[c], 1);
            if (sl < CAP) jbuf[c * CAP + sl] = (unsigned short)s;
        }
    }
    __syncthreads();

    // ---- selection + filters + emit: one lane per center ----
    if (tid < CPB) {
        const int    rk2 = cb + tid;
        const float4 c0  = s4[rk2];
        const float  ax = c0.x, ay = c0.y, az = c0.z, asq = c0.w;

        unsigned long long hd[KNN];
#pragma unroll
        for (int t = 0; t < KNN; ++t) hd[t] = ~0ull;

        const int m = cnt[tid];
        if (m <= CAP) {
            for (int e = 0; e < m; ++e) {
                const int s = jbuf[tid * CAP + e];
                float d2 = d2_ref(ax, ay, az, asq, s4[s]);
                // key: d2, then ORIG index (top_k tie semantics), then rank
                unsigned long long key =
                    ((unsigned long long)sortkey(d2) << 32) |
                    ((unsigned)si[s] << 16) | (unsigned)s;
                if (key < hd[KNN - 1]) {
#pragma unroll
                    for (int t = 0; t < KNN; ++t) {
                        unsigned long long lo = key < hd[t] ? key : hd[t];
                        unsigned long long hi = key < hd[t] ? hd[t] : key;
                        hd[t] = lo; key = hi;
                    }
                }
            }
        } else {
            // overflow fallback: exact full scan over all ranks
            for (int s = 0; s < NPG; ++s) {
                if (s == rk2) continue;
                float d2 = d2_ref(ax, ay, az, asq, s4[s]);
                unsigned long long key =
                    ((unsigned long long)sortkey(d2) << 32) |
                    ((unsigned)si[s] << 16) | (unsigned)s;
                if (key < hd[KNN - 1]) {
#pragma unroll
                    for (int t = 0; t < KNN; ++t) {
                        unsigned long long lo = key < hd[t] ? key : hd[t];
                        unsigned long long hi = key < hd[t] ? hd[t] : key;
                        hd[t] = lo; key = hi;
                    }
                }
            }
        }

        const int ctr = gb + si[rk2];
#pragma unroll
        for (int k = 0; k < KNN; ++k) {
            float2 e = make_float2(-1.0f, -1.0f);
            if (hd[k] != ~0ull) {
                const int sr  = (int)(hd[k] & 0xFFFFull);          // rank
                const int nbr = gb + (int)((hd[k] >> 16) & 0xFFFFull); // orig
                const float4 v = s4[sr];
                // degenerate-edge filter, reference formula
                float dx = __fadd_rn(v.x, -ax);
                float dy = __fadd_rn(v.y, -ay);
                float dz = __fadd_rn(v.z, -az);
                float dn2 = __fadd_rn(__fadd_rn(__fmul_rn(dx, dx),
                                                __fmul_rn(dy, dy)),
                                      __fmul_rn(dz, dz));
                int  rd    = nbr > ctr ? (nbr - ctr) : (ctr - nbr);
                bool valid = (rd >= MIN_DISTR) && (sqrtf(dn2) >= 1e-10f);
                if (valid) e = make_float2((float)nbr, (float)ctr);
            }
            out[ctr * KNN + k] = e;
        }
    }
}

extern "C" void kernel_launch(void* const* d_in, const int* in_sizes, int n_in,
                              void* d_out, int out_size)
{
    const float* pos = (const float*)d_in[0];
    for (int i = 0; i < n_in; ++i)
        if (in_sizes[i] == N_ALL * 3) { pos = (const float*)d_in[i]; break; }
    float2* out = (float2*)d_out;

    sort_kernel<<<BGRAPHS, 512>>>(pos);                    // 16 blocks
    knn_kernel<<<BGRAPHS * (NPG / CPB), THREADS>>>(out);   // 1024 blocks
}

// round 13
// speedup vs baseline: 2.1090x; 2.1090x over previous
#include <cuda_runtime.h>
#include <cstdint>

#define BGRAPHS   16
#define NPG       2048
#define KNN       16
#define MIN_DISTR 5
#define CPB       32                 // centers per block
#define PARTS     8                  // threads per center
#define CANDS     (NPG / PARTS)      // 256 candidates per part
#define SUB       4                  // pass-1 subsample stride
#define SCANDS    (CANDS / SUB)      // 64 pass-1 candidates per part
#define THREADS   (CPB * PARTS)      // 256 threads per block
#define CAP       160                // pass-2 collection capacity per center

// monotone float -> uint key (total order matching float <)
__device__ __forceinline__ unsigned sortkey(float f)
{
    unsigned u = __float_as_uint(f);
    return u ^ (unsigned)(((int)u >> 31) | 0x80000000);
}

// exact reference-rounded squared distance (validated rounds 3-12)
__device__ __forceinline__ float d2_ref(float cx, float cy, float cz, float csq,
                                        const float4 v)
{
    float dot = __fmaf_rn(cz, v.z, __fmaf_rn(cy, v.y, __fmul_rn(cx, v.x)));
    return __fmaf_rn(-2.0f, dot, __fadd_rn(csq, v.w));
}

__global__ __launch_bounds__(THREADS, 5)
void knn_kernel(const float* __restrict__ pos, float2* __restrict__ out)
{
    __shared__ float4         sh[NPG];                 // 32768 B: x,y,z,|p|^2
    __shared__ float          pvals[CPB * PARTS * 3];  //  3072 B
    __shared__ float          bnd[CPB];                //   128 B
    __shared__ int            cnt[CPB];                //   128 B
    __shared__ unsigned short jbuf[CPB * CAP];         // 10240 B  (total ~45.3 KB)

    const int tid = threadIdx.x;
    const int p   = tid >> 5;        // part 0..7 (uniform per warp)
    const int c   = tid & 31;        // center-in-block (lane)

    const int g  = blockIdx.x >> 6;           // 64 blocks per graph
    const int cb = (blockIdx.x & 63) * CPB;   // center base (local)
    const int gb = g * NPG;

    if (tid < CPB) cnt[tid] = 0;

    // ---- load graph into smem: {x,y,z,|p|^2} (sq per reference rounding) ----
    for (int i = tid; i < NPG; i += THREADS) {
        const float* q = pos + 3ull * (unsigned long long)(gb + i);
        float x = q[0], y = q[1], z = q[2];
        float sq = __fadd_rn(__fadd_rn(__fmul_rn(x, x), __fmul_rn(y, y)),
                             __fmul_rn(z, z));
        sh[i] = make_float4(x, y, z, sq);
    }
    __syncthreads();

    const int    lc = cb + c;
    const float4 cc = sh[lc];
    const float  cx = cc.x, cy = cc.y, cz = cc.z, csq = cc.w;
    const float  INF = __int_as_float(0x7f800000);

    // ---- pass 1 (bound): 3-smallest per part over a strided 1/4 subset ----
    // No self-check: self may flow through (handled by 17th-smallest bound).
    // Warp-uniform j -> broadcast LDS; fixed trip count -> no divergence.
    float h0 = INF, h1 = INF, h2 = INF;
    const int jb = p * CANDS;
#pragma unroll 8
    for (int t = 0; t < SCANDS; ++t) {
        float d2 = d2_ref(cx, cy, cz, csq, sh[jb + t * SUB]);
        float t0 = fminf(h0, d2), x1 = fmaxf(h0, d2); h0 = t0;
        float t1 = fminf(h1, x1), x2 = fmaxf(h1, x1); h1 = t1;
        h2 = fminf(h2, x2);
    }
    {
        float* pv = pvals + (c * PARTS + p) * 3;
        pv[0] = h0; pv[1] = h1; pv[2] = h2;
    }
    __syncthreads();

    // ---- bound: 17th smallest of the 24 kept values (= 8th largest) ----
    // >=17 real elements <= B, at most one is self => >=16 non-self <= B
    // => B >= true 16th-smallest non-self d2.  (subset => still an upper bound)
    if (tid < CPB) {
        float g8[8];
#pragma unroll
        for (int t = 0; t < 8; ++t) g8[t] = -INF;
        const float* pv = pvals + tid * PARTS * 3;
        for (int e = 0; e < PARTS * 3; ++e) {
            float x = pv[e];
#pragma unroll
            for (int t = 0; t < 8; ++t) {
                float hi = fmaxf(g8[t], x);
                x = fminf(g8[t], x);
                g8[t] = hi;
            }
        }
        bnd[tid] = g8[7];
    }
    __syncthreads();

    // ---- pass 2: collect candidate indices with d2 <= B (self included) ----
    const float B = bnd[c];
#pragma unroll 4
    for (int j = jb; j < jb + CANDS; ++j) {
        float dd = d2_ref(cx, cy, cz, csq, sh[j]);
        if (dd <= B) {
            int s = atomicAdd(&cnt[c], 1);
            if (s < CAP) jbuf[c * CAP + s] = (unsigned short)j;
        }
    }
    __syncthreads();

    // ---- selection + filters + emit: one lane per center ----
    if (tid < CPB) {
        const int    lc2 = cb + tid;
        const float4 c0  = sh[lc2];
        const float  ax = c0.x, ay = c0.y, az = c0.z, asq = c0.w;

        unsigned long long hd[KNN];
#pragma unroll
        for (int t = 0; t < KNN; ++t) hd[t] = ~0ull;

        const int m = cnt[tid];
        if (m <= CAP) {
            for (int e = 0; e < m; ++e) {
                const int j = jbuf[tid * CAP + e];
                if (j == lc2) continue;          // skip self
                float d2 = d2_ref(ax, ay, az, asq, sh[j]);
                unsigned long long key =
                    ((unsigned long long)sortkey(d2) << 32) | (unsigned)j;
                if (key < hd[KNN - 1]) {
#pragma unroll
                    for (int t = 0; t < KNN; ++t) {
                        unsigned long long lo = key < hd[t] ? key : hd[t];
                        unsigned long long hi = key < hd[t] ? hd[t] : key;
                        hd[t] = lo; key = hi;
                    }
                }
            }
        } else {
            // overflow fallback: exact full scan (deterministic)
            for (int j = 0; j < NPG; ++j) {
                if (j == lc2) continue;
                float d2 = d2_ref(ax, ay, az, asq, sh[j]);
                unsigned long long key =
                    ((unsigned long long)sortkey(d2) << 32) | (unsigned)j;
                if (key < hd[KNN - 1]) {
#pragma unroll
                    for (int t = 0; t < KNN; ++t) {
                        unsigned long long lo = key < hd[t] ? key : hd[t];
                        unsigned long long hi = key < hd[t] ? hd[t] : key;
                        hd[t] = lo; key = hi;
                    }
                }
            }
        }

        const int ctr = gb + lc2;
#pragma unroll
        for (int k = 0; k < KNN; ++k) {
            float2 e = make_float2(-1.0f, -1.0f);
            if (hd[k] != ~0ull) {
                const int nl  = (int)(unsigned)(hd[k] & 0xFFFFFFFFull);
                const int nbr = gb + nl;
                const float4 v = sh[nl];
                // degenerate-edge filter, reference formula
                float dx = __fadd_rn(v.x, -ax);
                float dy = __fadd_rn(v.y, -ay);
                float dz = __fadd_rn(v.z, -az);
                float dn2 = __fadd_rn(__fadd_rn(__fmul_rn(dx, dx),
                                                __fmul_rn(dy, dy)),
                                      __fmul_rn(dz, dz));
                int  rd    = nbr > ctr ? (nbr - ctr) : (ctr - nbr);
                bool valid = (rd >= MIN_DISTR) && (sqrtf(dn2) >= 1e-10f);
                if (valid) e = make_float2((float)nbr, (float)ctr);
            }
            out[ctr * KNN + k] = e;
        }
    }
}

extern "C" void kernel_launch(void* const* d_in, const int* in_sizes, int n_in,
                              void* d_out, int out_size)
{
    const float* pos = (const float*)d_in[0];
    for (int i = 0; i < n_in; ++i)
        if (in_sizes[i] == BGRAPHS * NPG * 3) { pos = (const float*)d_in[i]; break; }
    float2* out = (float2*)d_out;

    dim3 grid(BGRAPHS * (NPG / CPB));   // 1024 blocks
    dim3 block(THREADS);                // 256 threads
    knn_kernel<<<grid, block>>>(pos, out);
}

// round 14
// speedup vs baseline: 6.0007x; 2.8453x over previous
#include <cuda_runtime.h>
#include <cstdint>

#define BGRAPHS   16
#define NPG       2048
#define KNN       16
#define MIN_DISTR 5
#define CPB       32                 // centers per block
#define PARTS     8                  // threads per center
#define CANDS     (NPG / PARTS)      // 256 candidates per part
#define THREADS   (CPB * PARTS)      // 256 threads per block
#define CAP       128                // pass-2 collection capacity per center

// monotone float -> uint key (total order matching float <)
__device__ __forceinline__ unsigned sortkey(float f)
{
    unsigned u = __float_as_uint(f);
    return u ^ (unsigned)(((int)u >> 31) | 0x80000000);
}

// exact reference-rounded squared distance (validated rounds 3-13)
__device__ __forceinline__ float d2_ref(float cx, float cy, float cz, float csq,
                                        const float4 v)
{
    float dot = __fmaf_rn(cz, v.z, __fmaf_rn(cy, v.y, __fmul_rn(cx, v.x)));
    return __fmaf_rn(-2.0f, dot, __fadd_rn(csq, v.w));
}

__global__ __launch_bounds__(THREADS, 5)
void knn_kernel(const float* __restrict__ pos, float2* __restrict__ out)
{
    __shared__ float4         sh[NPG];                 // 32768 B: x,y,z,|p|^2
    __shared__ float          pvals[CPB * PARTS * 3];  //  3072 B: per-part 3 smallest
    __shared__ float          bnd[CPB];                //   128 B
    __shared__ int            cnt[CPB];                //   128 B
    __shared__ unsigned short jbuf[CPB * CAP];         //  8192 B

    const int tid = threadIdx.x;
    const int p   = tid >> 5;        // part 0..7 (uniform per warp)
    const int c   = tid & 31;        // center-in-block (lane)

    const int g  = blockIdx.x >> 6;           // 64 blocks per graph
    const int cb = (blockIdx.x & 63) * CPB;   // center base (local)
    const int gb = g * NPG;

    if (tid < CPB) cnt[tid] = 0;

    // ---- load graph into smem: {x,y,z,|p|^2} (sq per reference rounding) ----
    for (int i = tid; i < NPG; i += THREADS) {
        const float* q = pos + 3ull * (unsigned long long)(gb + i);
        float x = q[0], y = q[1], z = q[2];
        float sq = __fadd_rn(__fadd_rn(__fmul_rn(x, x), __fmul_rn(y, y)),
                             __fmul_rn(z, z));
        sh[i] = make_float4(x, y, z, sq);
    }
    __syncthreads();

    const int    lc = cb + c;
    const float4 cc = sh[lc];
    const float  cx = cc.x, cy = cc.y, cz = cc.z, csq = cc.w;
    const float  INF = __int_as_float(0x7f800000);

    // ---- pass 1: 3 smallest of this part's FULL substream, branchless ----
    // NO self-check: self flows through as an ordinary element; the bound
    // below compensates by taking the 17th-smallest instead of 16th.
    float h0 = INF, h1 = INF, h2 = INF;
    const int jb = p * CANDS;
#pragma unroll 8
    for (int j = jb; j < jb + CANDS; ++j) {
        float d2 = d2_ref(cx, cy, cz, csq, sh[j]);
        float t0 = fminf(h0, d2), x1 = fmaxf(h0, d2); h0 = t0;
        float t1 = fminf(h1, x1), x2 = fmaxf(h1, x1); h1 = t1;
        h2 = fminf(h2, x2);
    }
    {
        float* pv = pvals + (c * PARTS + p) * 3;
        pv[0] = h0; pv[1] = h1; pv[2] = h2;
    }
    __syncthreads();

    // ---- bound: 17th smallest of the 24 kept values (= 8th largest) ----
    // >=17 distinct elements <= B, at most one is self => >=16 non-self <= B
    // => B >= true 16th-smallest non-self d2.
    if (tid < CPB) {
        float g8[8];
#pragma unroll
        for (int t = 0; t < 8; ++t) g8[t] = -INF;
        const float* pv = pvals + tid * PARTS * 3;
        for (int e = 0; e < PARTS * 3; ++e) {
            float x = pv[e];
#pragma unroll
            for (int t = 0; t < 8; ++t) {
                float hi = fmaxf(g8[t], x);
                x = fminf(g8[t], x);
                g8[t] = hi;
            }
        }
        bnd[tid] = g8[7];
    }
    __syncthreads();

    // ---- pass 2: collect candidate indices with d2 <= B (self included) ----
    const float B = bnd[c];
#pragma unroll 4
    for (int j = jb; j < jb + CANDS; ++j) {
        float dd = d2_ref(cx, cy, cz, csq, sh[j]);
        if (dd <= B) {
            int s = atomicAdd(&cnt[c], 1);
            if (s < CAP) jbuf[c * CAP + s] = (unsigned short)j;
        }
    }
    __syncthreads();

    // ---- selection + filters + emit: one lane per center ----
    if (tid < CPB) {
        const int    lc2 = cb + tid;
        const float4 c0  = sh[lc2];
        const float  ax = c0.x, ay = c0.y, az = c0.z, asq = c0.w;

        unsigned long long hd[KNN];
#pragma unroll
        for (int t = 0; t < KNN; ++t) hd[t] = ~0ull;

        const int m = cnt[tid];
        if (m <= CAP) {
            for (int e = 0; e < m; ++e) {
                const int j = jbuf[tid * CAP + e];
                if (j == lc2) continue;          // skip self (collected above)
                float d2 = d2_ref(ax, ay, az, asq, sh[j]);
                unsigned long long key =
                    ((unsigned long long)sortkey(d2) << 32) | (unsigned)j;
                if (key < hd[KNN - 1]) {
#pragma unroll
                    for (int t = 0; t < KNN; ++t) {
                        unsigned long long lo = key < hd[t] ? key : hd[t];
                        unsigned long long hi = key < hd[t] ? hd[t] : key;
                        hd[t] = lo; key = hi;
                    }
                }
            }
        } else {
            // overflow fallback: exact full scan (deterministic, ~never)
            for (int j = 0; j < NPG; ++j) {
                if (j == lc2) continue;
                float d2 = d2_ref(ax, ay, az, asq, sh[j]);
                unsigned long long key =
                    ((unsigned long long)sortkey(d2) << 32) | (unsigned)j;
                if (key < hd[KNN - 1]) {
#pragma unroll
                    for (int t = 0; t < KNN; ++t) {
                        unsigned long long lo = key < hd[t] ? key : hd[t];
                        unsigned long long hi = key < hd[t] ? hd[t] : key;
                        hd[t] = lo; key = hi;
                    }
                }
            }
        }

        const int ctr = gb + lc2;
#pragma unroll
        for (int k = 0; k < KNN; ++k) {
            float2 e = make_float2(-1.0f, -1.0f);
            if (hd[k] != ~0ull) {
                const int nl  = (int)(unsigned)(hd[k] & 0xFFFFFFFFull);
                const int nbr = gb + nl;
                const float4 v = sh[nl];
                // degenerate-edge filter, reference formula
                float dx = __fadd_rn(v.x, -ax);
                float dy = __fadd_rn(v.y, -ay);
                float dz = __fadd_rn(v.z, -az);
                float dn2 = __fadd_rn(__fadd_rn(__fmul_rn(dx, dx),
                                                __fmul_rn(dy, dy)),
                                      __fmul_rn(dz, dz));
                int  rd    = nbr > ctr ? (nbr - ctr) : (ctr - nbr);
                bool valid = (rd >= MIN_DISTR) && (sqrtf(dn2) >= 1e-10f);
                if (valid) e = make_float2((float)nbr, (float)ctr);
            }
            out[ctr * KNN + k] = e;
        }
    }
}

extern "C" void kernel_launch(void* const* d_in, const int* in_sizes, int n_in,
                              void* d_out, int out_size)
{
    const float* pos = (const float*)d_in[0];
    for (int i = 0; i < n_in; ++i)
        if (in_sizes[i] == BGRAPHS * NPG * 3) { pos = (const float*)d_in[i]; break; }
    float2* out = (float2*)d_out;

    dim3 grid(BGRAPHS * (NPG / CPB));   // 1024 blocks
    dim3 block(THREADS);                // 256 threads
    knn_kernel<<<grid, block>>>(pos, out);
}

// round 15
// speedup vs baseline: 6.2504x; 1.0416x over previous
#include <cuda_runtime.h>
#include <cstdint>

#define BGRAPHS   16
#define NPG       2048
#define KNN       16
#define MIN_DISTR 5
#define CPB       32                 // centers per block
#define PARTS     8                  // threads per center
#define CANDS     (NPG / PARTS)      // 256 candidates per part
#define THREADS   (CPB * PARTS)      // 256 threads per block
#define CAP       128                // pass-2 collection capacity per center
#define TMARGIN   0.01f              // covers |d2 - (t + csq)| rounding (<=~6e-4)

// monotone float -> uint key (total order matching float <)
__device__ __forceinline__ unsigned sortkey(float f)
{
    unsigned u = __float_as_uint(f);
    return u ^ (unsigned)(((int)u >> 31) | 0x80000000);
}

// exact reference-rounded squared distance (validated rounds 3-14) — selection only
__device__ __forceinline__ float d2_ref(float cx, float cy, float cz, float csq,
                                        const float4 v)
{
    float dot = __fmaf_rn(cz, v.z, __fmaf_rn(cy, v.y, __fmul_rn(cx, v.x)));
    return __fmaf_rn(-2.0f, dot, __fadd_rn(csq, v.w));
}

// cheap surrogate: t = fma(-2, dot, w). Order(t) == Order(d2) shifted by csq,
// up to <=~6e-4 discrepancy (absorbed by TMARGIN). One FADD cheaper per call.
__device__ __forceinline__ float t_surr(float cx, float cy, float cz,
                                        const float4 v)
{
    float dot = __fmaf_rn(cz, v.z, __fmaf_rn(cy, v.y, __fmul_rn(cx, v.x)));
    return __fmaf_rn(-2.0f, dot, v.w);
}

__global__ __launch_bounds__(THREADS, 5)
void knn_kernel(const float* __restrict__ pos, float2* __restrict__ out)
{
    __shared__ float4         sh[NPG];                 // 32768 B: x,y,z,|p|^2
    __shared__ float          pvals[CPB * PARTS * 3];  //  3072 B: per-part 3 smallest t
    __shared__ float          bnd[CPB];                //   128 B
    __shared__ int            cnt[CPB];                //   128 B
    __shared__ unsigned short jbuf[CPB * CAP];         //  8192 B

    const int tid = threadIdx.x;
    const int p   = tid >> 5;        // part 0..7 (uniform per warp)
    const int c   = tid & 31;        // center-in-block (lane)

    const int g  = blockIdx.x >> 6;           // 64 blocks per graph
    const int cb = (blockIdx.x & 63) * CPB;   // center base (local)
    const int gb = g * NPG;

    if (tid < CPB) cnt[tid] = 0;

    // ---- load graph into smem: {x,y,z,|p|^2} (sq per reference rounding) ----
    for (int i = tid; i < NPG; i += THREADS) {
        const float* q = pos + 3ull * (unsigned long long)(gb + i);
        float x = q[0], y = q[1], z = q[2];
        float sq = __fadd_rn(__fadd_rn(__fmul_rn(x, x), __fmul_rn(y, y)),
                             __fmul_rn(z, z));
        sh[i] = make_float4(x, y, z, sq);
    }
    __syncthreads();

    const int    lc = cb + c;
    const float4 cc = sh[lc];
    const float  cx = cc.x, cy = cc.y, cz = cc.z;
    const float  INF = __int_as_float(0x7f800000);

    // ---- pass 1: 3 smallest t of this part's FULL substream, branchless ----
    // No self-check (self's t ~ -csq is very small; tolerated by 17th bound).
    float h0 = INF, h1 = INF, h2 = INF;
    const int jb = p * CANDS;
#pragma unroll 8
    for (int j = jb; j < jb + CANDS; ++j) {
        float t = t_surr(cx, cy, cz, sh[j]);
        float t0 = fminf(h0, t),  x1 = fmaxf(h0, t);  h0 = t0;
        float t1 = fminf(h1, x1), x2 = fmaxf(h1, x1); h1 = t1;
        h2 = fminf(h2, x2);
    }
    {
        float* pv = pvals + (c * PARTS + p) * 3;
        pv[0] = h0; pv[1] = h1; pv[2] = h2;
    }
    __syncthreads();

    // ---- bound: 17th smallest of the 24 kept t (= 8th largest) + margin ----
    // >=17 elements with t <= B_t; at most one is self => >=16 non-self.
    // TMARGIN absorbs the t<->d2 constant-shift rounding discrepancy, so any
    // exact-d2 top-16 element must satisfy t <= B_t + TMARGIN.
    if (tid < CPB) {
        float g8[8];
#pragma unroll
        for (int t = 0; t < 8; ++t) g8[t] = -INF;
        const float* pv = pvals + tid * PARTS * 3;
        for (int e = 0; e < PARTS * 3; ++e) {
            float x = pv[e];
#pragma unroll
            for (int t = 0; t < 8; ++t) {
                float hi = fmaxf(g8[t], x);
                x = fminf(g8[t], x);
                g8[t] = hi;
            }
        }
        bnd[tid] = g8[7] + TMARGIN;
    }
    __syncthreads();

    // ---- pass 2: collect candidates with t <= B (bit-identical t recompute) ----
    const float B = bnd[c];
#pragma unroll 4
    for (int j = jb; j < jb + CANDS; ++j) {
        float t = t_surr(cx, cy, cz, sh[j]);
        if (t <= B) {
            int s = atomicAdd(&cnt[c], 1);
            if (s < CAP) jbuf[c * CAP + s] = (unsigned short)j;
        }
    }
    __syncthreads();

    // ---- selection (exact d2) + filters + emit: one lane per center ----
    if (tid < CPB) {
        const int    lc2 = cb + tid;
        const float4 c0  = sh[lc2];
        const float  ax = c0.x, ay = c0.y, az = c0.z, asq = c0.w;

        unsigned long long hd[KNN];
#pragma unroll
        for (int t = 0; t < KNN; ++t) hd[t] = ~0ull;

        const int m = cnt[tid];
        if (m <= CAP) {
            for (int e = 0; e < m; ++e) {
                const int j = jbuf[tid * CAP + e];
                if (j == lc2) continue;          // skip self (collected above)
                float d2 = d2_ref(ax, ay, az, asq, sh[j]);
                unsigned long long key =
                    ((unsigned long long)sortkey(d2) << 32) | (unsigned)j;
                if (key < hd[KNN - 1]) {
#pragma unroll
                    for (int t = 0; t < KNN; ++t) {
                        unsigned long long lo = key < hd[t] ? key : hd[t];
                        unsigned long long hi = key < hd[t] ? hd[t] : key;
                        hd[t] = lo; key = hi;
                    }
                }
            }
        } else {
            // overflow fallback: exact full scan (deterministic, ~never)
            for (int j = 0; j < NPG; ++j) {
                if (j == lc2) continue;
                float d2 = d2_ref(ax, ay, az, asq, sh[j]);
                unsigned long long key =
                    ((unsigned long long)sortkey(d2) << 32) | (unsigned)j;
                if (key < hd[KNN - 1]) {
#pragma unroll
                    for (int t = 0; t < KNN; ++t) {
                        unsigned long long lo = key < hd[t] ? key : hd[t];
                        unsigned long long hi = key < hd[t] ? hd[t] : key;
                        hd[t] = lo; key = hi;
                    }
                }
            }
        }

        const int ctr = gb + lc2;
#pragma unroll
        for (int k = 0; k < KNN; ++k) {
            float2 e = make_float2(-1.0f, -1.0f);
            if (hd[k] != ~0ull) {
                const int nl  = (int)(unsigned)(hd[k] & 0xFFFFFFFFull);
                const int nbr = gb + nl;
                const float4 v = sh[nl];
                // degenerate-edge filter, reference formula
                float dx = __fadd_rn(v.x, -ax);
                float dy = __fadd_rn(v.y, -ay);
                float dz = __fadd_rn(v.z, -az);
                float dn2 = __fadd_rn(__fadd_rn(__fmul_rn(dx, dx),
                                                __fmul_rn(dy, dy)),
                                      __fmul_rn(dz, dz));
                int  rd    = nbr > ctr ? (nbr - ctr) : (ctr - nbr);
                bool valid = (rd >= MIN_DISTR) && (sqrtf(dn2) >= 1e-10f);
                if (valid) e = make_float2((float)nbr, (float)ctr);
            }
            out[ctr * KNN + k] = e;
        }
    }
}

extern "C" void kernel_launch(void* const* d_in, const int* in_sizes, int n_in,
                              void* d_out, int out_size)
{
    const float* pos = (const float*)d_in[0];
    for (int i = 0; i < n_in; ++i)
        if (in_sizes[i] == BGRAPHS * NPG * 3) { pos = (const float*)d_in[i]; break; }
    float2* out = (float2*)d_out;

    dim3 grid(BGRAPHS * (NPG / CPB));   // 1024 blocks
    dim3 block(THREADS);                // 256 threads
    knn_kernel<<<grid, block>>>(pos, out);
}